// round 1
// baseline (speedup 1.0000x reference)
#include <cuda_runtime.h>
#include <math.h>

#define DD 64
#define MAXN 50176
#define MAXR 256

// Scratch (static device globals — no allocation anywhere)
__device__ float g_XA[MAXN * DD];    // n_feats @ W_I^T
__device__ float g_XB[MAXN * DD];    // n_feats @ W_O^T
__device__ float g_seg[MAXN * DD];   // segment sums
__device__ float g_deg[MAXN];        // degrees
__device__ float g_RI[MAXR * DD];    // r @ W_I^T - b_I
__device__ float g_RO[MAXR * DD];    // r @ W_O^T - b_O

// ---------------------------------------------------------------------------
// Zero segment accumulators + degrees
// ---------------------------------------------------------------------------
__global__ void zero_kernel(int n) {
    int stride = gridDim.x * blockDim.x;
    int tid = blockIdx.x * blockDim.x + threadIdx.x;
    float4 z = make_float4(0.f, 0.f, 0.f, 0.f);
    float4* seg4 = reinterpret_cast<float4*>(g_seg);
    int total4 = n * (DD / 4);
    for (int i = tid; i < total4; i += stride) seg4[i] = z;
    for (int i = tid; i < n; i += stride) g_deg[i] = 0.f;
}

// ---------------------------------------------------------------------------
// Per-relation tables: RI = r@W_I^T - b_I, RO = r@W_O^T - b_O,
// r_out = r@W_R^T + b_R.  One block per relation, 64 threads (j = out col).
// ---------------------------------------------------------------------------
__global__ void rel_kernel(const float* __restrict__ rf,
                           const float* __restrict__ WI, const float* __restrict__ bI,
                           const float* __restrict__ WO, const float* __restrict__ bO,
                           const float* __restrict__ WR, const float* __restrict__ bR,
                           float* __restrict__ r_out) {
    __shared__ float rs[DD];
    int t = blockIdx.x;
    int j = threadIdx.x;
    rs[j] = rf[t * DD + j];
    __syncthreads();
    float aI = 0.f, aO = 0.f, aR = 0.f;
#pragma unroll 8
    for (int k = 0; k < DD; k++) {
        float v = rs[k];
        aI += v * WI[j * DD + k];
        aO += v * WO[j * DD + k];
        aR += v * WR[j * DD + k];
    }
    g_RI[t * DD + j] = aI - bI[j];
    g_RO[t * DD + j] = aO - bO[j];
    r_out[t * DD + j] = aR + bR[j];
}

// ---------------------------------------------------------------------------
// Node transform: XA = nf @ WI^T, XB = nf @ WO^T.
// Block = 128 threads, tile = 64 rows x 128 cols (cols 0-63 -> XA, 64-127 -> XB)
// Thread tile 8x8. Static smem = 16KB (x) + 32KB (both W, transposed) = 48KB.
// ---------------------------------------------------------------------------
__global__ void __launch_bounds__(128) node_transform(
    const float* __restrict__ nf,
    const float* __restrict__ WI,
    const float* __restrict__ WO,
    int N) {
    __shared__ float sx[64 * 64];    // sx[r][k], row-major
    __shared__ float sw[64 * 128];   // sw[k][c]: c<64 -> WI[c][k], else WO[c-64][k]

    int tid = threadIdx.x;
    int row0 = blockIdx.x * 64;

    // Load weights transposed (strided gmem reads, L1/L2-cached; one-time cost)
    for (int i = tid; i < 64 * 64; i += 128) {
        int j = i & 63;        // output col
        int k = i >> 6;        // input dim
        sw[k * 128 + j]      = WI[j * 64 + k];
        sw[k * 128 + 64 + j] = WO[j * 64 + k];
    }
    // Load x tile (float4, coalesced)
    for (int i = tid; i < 64 * 16; i += 128) {
        int r  = i >> 4;
        int c4 = (i & 15) * 4;
        float4 v = make_float4(0.f, 0.f, 0.f, 0.f);
        int row = row0 + r;
        if (row < N) v = *reinterpret_cast<const float4*>(nf + (size_t)row * 64 + c4);
        sx[r * 64 + c4 + 0] = v.x;
        sx[r * 64 + c4 + 1] = v.y;
        sx[r * 64 + c4 + 2] = v.z;
        sx[r * 64 + c4 + 3] = v.w;
    }
    __syncthreads();

    int trow = tid >> 4;        // 0..7
    int tcol = tid & 15;        // 0..15
    int r0 = trow * 8;

    float acc[8][8];
#pragma unroll
    for (int i = 0; i < 8; i++)
#pragma unroll
        for (int j = 0; j < 8; j++) acc[i][j] = 0.f;

#pragma unroll 4
    for (int k = 0; k < 64; k++) {
        float a[8], w[8];
#pragma unroll
        for (int i = 0; i < 8; i++) a[i] = sx[(r0 + i) * 64 + k];
#pragma unroll
        for (int j = 0; j < 8; j++) w[j] = sw[k * 128 + tcol + 16 * j];
#pragma unroll
        for (int i = 0; i < 8; i++)
#pragma unroll
            for (int j = 0; j < 8; j++) acc[i][j] += a[i] * w[j];
    }

#pragma unroll
    for (int i = 0; i < 8; i++) {
        int row = row0 + r0 + i;
        if (row < N) {
#pragma unroll
            for (int j = 0; j < 8; j++) {
                int c = tcol + 16 * j;
                if (c < 64) g_XA[(size_t)row * 64 + c]        = acc[i][j];
                else        g_XB[(size_t)row * 64 + (c - 64)] = acc[i][j];
            }
        }
    }
}

// ---------------------------------------------------------------------------
// Edge kernel: 16 lanes per edge; each lane handles one float4 of D=64.
// value = (t < half ? XA[s] - RI[t] : XB[s] - RO[t]); red.v4 into g_seg[dst].
// ---------------------------------------------------------------------------
__global__ void edge_kernel(const int* __restrict__ src,
                            const int* __restrict__ dst,
                            const int* __restrict__ etype,
                            int E, const int* __restrict__ nrptr, int half_fallback) {
    int gt = blockIdx.x * blockDim.x + threadIdx.x;
    int e = gt >> 4;
    int sub = gt & 15;
    if (e >= E) return;

    int half = half_fallback;
    if (nrptr) half = nrptr[0] >> 1;

    int s = src[e];
    int d = dst[e];
    int t = etype[e];

    const float4* xr;
    const float4* rr;
    if (t < half) {
        xr = reinterpret_cast<const float4*>(g_XA) + (size_t)s * 16;
        rr = reinterpret_cast<const float4*>(g_RI) + (size_t)t * 16;
    } else {
        xr = reinterpret_cast<const float4*>(g_XB) + (size_t)s * 16;
        rr = reinterpret_cast<const float4*>(g_RO) + (size_t)t * 16;
    }
    float4 x = xr[sub];
    float4 r = rr[sub];
    float4 v = make_float4(x.x - r.x, x.y - r.y, x.z - r.z, x.w - r.w);

    float* p = g_seg + (size_t)d * 64 + sub * 4;
    asm volatile("red.global.add.v4.f32 [%0], {%1, %2, %3, %4};"
                 :: "l"(p), "f"(v.x), "f"(v.y), "f"(v.z), "f"(v.w)
                 : "memory");
    if (sub == 0) atomicAdd(&g_deg[d], 1.0f);
}

// ---------------------------------------------------------------------------
// Finalize: out = seg / max(deg, 1)
// ---------------------------------------------------------------------------
__global__ void finalize_kernel(float* __restrict__ out, int n) {
    int i = blockIdx.x * blockDim.x + threadIdx.x;
    int total4 = n * 16;
    if (i >= total4) return;
    int v = i >> 4;
    float inv = 1.0f / fmaxf(g_deg[v], 1.0f);
    float4 s = reinterpret_cast<const float4*>(g_seg)[i];
    reinterpret_cast<float4*>(out)[i] = make_float4(s.x * inv, s.y * inv, s.z * inv, s.w * inv);
}

// ---------------------------------------------------------------------------
extern "C" void kernel_launch(void* const* d_in, const int* in_sizes, int n_in,
                              void* d_out, int out_size) {
    const float* nf = (const float*)d_in[0];
    const float* rf = (const float*)d_in[1];
    const float* WI = (const float*)d_in[2];
    const float* bI = (const float*)d_in[3];
    const float* WO = (const float*)d_in[4];
    const float* bO = (const float*)d_in[5];
    const float* WR = (const float*)d_in[6];
    const float* bR = (const float*)d_in[7];
    const int* src  = (const int*)d_in[8];
    const int* dst  = (const int*)d_in[9];
    const int* et   = (const int*)d_in[10];
    const int* nrp  = (n_in > 11) ? (const int*)d_in[11] : nullptr;

    int Dv = in_sizes[3];            // = 64
    int N  = in_sizes[0] / Dv;
    int R  = in_sizes[1] / Dv;
    int E  = in_sizes[8];
    float* out = (float*)d_out;
    float* r_out = out + (size_t)N * Dv;

    // 1) zero accumulators
    {
        int total4 = N * 16;
        int blocks = (total4 + 255) / 256;
        zero_kernel<<<blocks, 256>>>(N);
    }
    // 2) relation tables + r_out
    rel_kernel<<<R, DD>>>(rf, WI, bI, WO, bO, WR, bR, r_out);
    // 3) node transform (XA, XB)
    {
        int blocks = (N + 63) / 64;
        node_transform<<<blocks, 128>>>(nf, WI, WO, N);
    }
    // 4) edge scatter
    {
        long long threads = (long long)E * 16;
        int blocks = (int)((threads + 255) / 256);
        edge_kernel<<<blocks, 256>>>(src, dst, et, E, nrp, R / 2);
    }
    // 5) finalize mean
    {
        int total4 = N * 16;
        int blocks = (total4 + 255) / 256;
        finalize_kernel<<<blocks, 256>>>(out, N);
    }
}

// round 2
// speedup vs baseline: 1.1647x; 1.1647x over previous
#include <cuda_runtime.h>
#include <math.h>

#define DD 64
#define MAXN   50176            // padded node cap (must be >= N, mult of 256)
#define MAXNB  256              // max scan blocks (N <= 65536)
#define MAXNPAD (MAXNB * 256)
#define MAXR 256
#define MAXE 2097152

// Scratch (static device globals — no allocation anywhere)
__device__ float g_X[2 * MAXN * DD];      // rows [0,N): nf@WI^T ; rows [N,2N): nf@WO^T
__device__ float g_R[2 * MAXR * DD];      // rows [0,R): r@WI^T - bI ; rows [256,256+R): r@WO^T - bO
__device__ int   g_cnt[MAXNPAD];          // per-dst degree
__device__ int   g_cur[MAXNPAD];          // reorder cursors
__device__ int   g_lex[MAXNPAD];          // block-local exclusive scan of counts
__device__ int   g_bsum[MAXNB];           // per-scan-block sums
__device__ int   g_base[MAXNB];           // exclusive scan of block sums
__device__ unsigned g_pack[MAXE];         // packed (row | trow<<17) per edge, CSR order

// ---------------------------------------------------------------------------
// Fused kernel 1: [zero counters] + [relation tables + r_out] + [node transform]
// dispatched by blockIdx range. 128 threads/block.
// ---------------------------------------------------------------------------
__global__ void __launch_bounds__(128) k_fused(
    const float* __restrict__ nf, const float* __restrict__ rf,
    const float* __restrict__ WI, const float* __restrict__ bI,
    const float* __restrict__ WO, const float* __restrict__ bO,
    const float* __restrict__ WR, const float* __restrict__ bR,
    float* __restrict__ r_out,
    int N, int R, int npad, int nbZero) {

    __shared__ float sx[64 * 64];    // NT: x tile   (rel reuses first 64)
    __shared__ float sw[64 * 128];   // NT: both W transposed

    int b = blockIdx.x;
    int tid = threadIdx.x;

    if (b < nbZero) {
        // ---- zero g_cnt, g_cur ----
        int stride = nbZero * 128;
        for (int i = b * 128 + tid; i < npad; i += stride) { g_cnt[i] = 0; g_cur[i] = 0; }
        return;
    }
    b -= nbZero;
    if (b < R) {
        // ---- relation tables: one block per relation, 64 active threads ----
        int t = b;
        int j = tid;
        if (j < DD) sx[j] = rf[t * DD + j];
        __syncthreads();
        if (j < DD) {
            float aI = 0.f, aO = 0.f, aR = 0.f;
#pragma unroll 8
            for (int k = 0; k < DD; k++) {
                float v = sx[k];
                aI += v * WI[j * DD + k];
                aO += v * WO[j * DD + k];
                aR += v * WR[j * DD + k];
            }
            g_R[t * DD + j]              = aI - bI[j];
            g_R[(MAXR + t) * DD + j]     = aO - bO[j];
            r_out[t * DD + j]            = aR + bR[j];
        }
        return;
    }
    b -= R;

    // ---- node transform: 64-row tile, outputs 128 cols (XA | XB) ----
    int row0 = b * 64;

    for (int i = tid; i < 64 * 64; i += 128) {
        int j = i & 63;        // output col
        int k = i >> 6;        // input dim
        sw[k * 128 + j]      = WI[j * 64 + k];
        sw[k * 128 + 64 + j] = WO[j * 64 + k];
    }
    for (int i = tid; i < 64 * 16; i += 128) {
        int r  = i >> 4;
        int c4 = (i & 15) * 4;
        float4 v = make_float4(0.f, 0.f, 0.f, 0.f);
        int row = row0 + r;
        if (row < N) v = *reinterpret_cast<const float4*>(nf + (size_t)row * 64 + c4);
        sx[r * 64 + c4 + 0] = v.x;
        sx[r * 64 + c4 + 1] = v.y;
        sx[r * 64 + c4 + 2] = v.z;
        sx[r * 64 + c4 + 3] = v.w;
    }
    __syncthreads();

    int trow = tid >> 4;        // 0..7
    int tcol = tid & 15;        // 0..15
    int r0 = trow * 8;

    float acc[8][8];
#pragma unroll
    for (int i = 0; i < 8; i++)
#pragma unroll
        for (int j = 0; j < 8; j++) acc[i][j] = 0.f;

#pragma unroll 4
    for (int k = 0; k < 64; k++) {
        float a[8], w[8];
#pragma unroll
        for (int i = 0; i < 8; i++) a[i] = sx[(r0 + i) * 64 + k];
#pragma unroll
        for (int j = 0; j < 8; j++) w[j] = sw[k * 128 + tcol + 16 * j];
#pragma unroll
        for (int i = 0; i < 8; i++)
#pragma unroll
            for (int j = 0; j < 8; j++) acc[i][j] += a[i] * w[j];
    }

#pragma unroll
    for (int i = 0; i < 8; i++) {
        int row = row0 + r0 + i;
        if (row < N) {
#pragma unroll
            for (int j = 0; j < 8; j++) {
                int c = tcol + 16 * j;
                if (c < 64) g_X[(size_t)row * 64 + c]            = acc[i][j];
                else        g_X[(size_t)(N + row) * 64 + (c - 64)] = acc[i][j];
            }
        }
    }
}

// ---------------------------------------------------------------------------
// Histogram of dst (int4 vectorized)
// ---------------------------------------------------------------------------
__global__ void k_hist(const int* __restrict__ dst, int E) {
    int i = blockIdx.x * blockDim.x + threadIdx.x;
    int e4 = E >> 2;
    if (i < e4) {
        int4 d = reinterpret_cast<const int4*>(dst)[i];
        atomicAdd(&g_cnt[d.x], 1);
        atomicAdd(&g_cnt[d.y], 1);
        atomicAdd(&g_cnt[d.z], 1);
        atomicAdd(&g_cnt[d.w], 1);
    }
    int rem = E & 3;
    if (i < rem) atomicAdd(&g_cnt[dst[e4 * 4 + i]], 1);
}

// ---------------------------------------------------------------------------
// Scan A: per-256-block exclusive scan of g_cnt + block sums
// ---------------------------------------------------------------------------
__global__ void k_scanA() {
    __shared__ int s[256];
    int t = threadIdx.x;
    int i = blockIdx.x * 256 + t;
    int v = g_cnt[i];
    s[t] = v;
    __syncthreads();
#pragma unroll
    for (int off = 1; off < 256; off <<= 1) {
        int x = (t >= off) ? s[t - off] : 0;
        __syncthreads();
        s[t] += x;
        __syncthreads();
    }
    g_lex[i] = s[t] - v;
    if (t == 255) g_bsum[blockIdx.x] = s[t];
}

// ---------------------------------------------------------------------------
// Scan B: exclusive scan of block sums (single block, carry loop)
// ---------------------------------------------------------------------------
__global__ void k_scanB(int nb) {
    __shared__ int s[256];
    int t = threadIdx.x;
    int carry = 0;
    for (int c0 = 0; c0 < nb; c0 += 256) {
        int idx = c0 + t;
        int v = (idx < nb) ? g_bsum[idx] : 0;
        s[t] = v;
        __syncthreads();
#pragma unroll
        for (int off = 1; off < 256; off <<= 1) {
            int x = (t >= off) ? s[t - off] : 0;
            __syncthreads();
            s[t] += x;
            __syncthreads();
        }
        if (idx < nb) g_base[idx] = s[t] - v + carry;
        carry += s[255];
        __syncthreads();
    }
}

// ---------------------------------------------------------------------------
// Reorder edges into CSR order, pre-resolving the I/O branch into row indices.
// pack = x_row(17b) | r_row << 17 (9b)
// ---------------------------------------------------------------------------
__global__ void k_reorder(const int* __restrict__ src, const int* __restrict__ dst,
                          const int* __restrict__ et, int E, int N,
                          const int* __restrict__ nrp, int halfFB) {
    int e = blockIdx.x * blockDim.x + threadIdx.x;
    if (e >= E) return;
    int half = nrp ? (nrp[0] >> 1) : halfFB;
    int d = dst[e];
    int s = src[e];
    int t = et[e];
    int pos = g_base[d >> 8] + g_lex[d] + atomicAdd(&g_cur[d], 1);
    unsigned row, trow;
    if (t < half) { row = (unsigned)s;       trow = (unsigned)t; }
    else          { row = (unsigned)(s + N); trow = (unsigned)(t + MAXR); }
    g_pack[pos] = row | (trow << 17);
}

// ---------------------------------------------------------------------------
// Gather + mean: one warp per node, float2 per lane, unroll-4 for MLP.
// ---------------------------------------------------------------------------
__global__ void __launch_bounds__(256) k_gather(float* __restrict__ out, int N) {
    int gid = blockIdx.x * 256 + threadIdx.x;
    int v = gid >> 5;
    int lane = gid & 31;
    if (v >= N) return;

    int start = g_base[v >> 8] + g_lex[v];
    int deg = g_cnt[v];
    const unsigned* __restrict__ pk = g_pack + start;
    const float2* __restrict__ X2 = reinterpret_cast<const float2*>(g_X);
    const float2* __restrict__ R2 = reinterpret_cast<const float2*>(g_R);

    float ax = 0.f, ay = 0.f;
    int i = 0;
    for (; i + 4 <= deg; i += 4) {
        unsigned p0 = pk[i], p1 = pk[i + 1], p2 = pk[i + 2], p3 = pk[i + 3];
        float2 x0 = X2[(size_t)(p0 & 0x1FFFF) * 32 + lane];
        float2 r0 = R2[(size_t)(p0 >> 17) * 32 + lane];
        float2 x1 = X2[(size_t)(p1 & 0x1FFFF) * 32 + lane];
        float2 r1 = R2[(size_t)(p1 >> 17) * 32 + lane];
        float2 x2 = X2[(size_t)(p2 & 0x1FFFF) * 32 + lane];
        float2 r2 = R2[(size_t)(p2 >> 17) * 32 + lane];
        float2 x3 = X2[(size_t)(p3 & 0x1FFFF) * 32 + lane];
        float2 r3 = R2[(size_t)(p3 >> 17) * 32 + lane];
        ax += (x0.x - r0.x) + (x1.x - r1.x) + (x2.x - r2.x) + (x3.x - r3.x);
        ay += (x0.y - r0.y) + (x1.y - r1.y) + (x2.y - r2.y) + (x3.y - r3.y);
    }
    for (; i < deg; i++) {
        unsigned p = pk[i];
        float2 x = X2[(size_t)(p & 0x1FFFF) * 32 + lane];
        float2 r = R2[(size_t)(p >> 17) * 32 + lane];
        ax += x.x - r.x;
        ay += x.y - r.y;
    }
    float inv = 1.0f / (float)(deg > 1 ? deg : 1);
    reinterpret_cast<float2*>(out)[(size_t)v * 32 + lane] =
        make_float2(ax * inv, ay * inv);
}

// ---------------------------------------------------------------------------
extern "C" void kernel_launch(void* const* d_in, const int* in_sizes, int n_in,
                              void* d_out, int out_size) {
    const float* nf = (const float*)d_in[0];
    const float* rf = (const float*)d_in[1];
    const float* WI = (const float*)d_in[2];
    const float* bI = (const float*)d_in[3];
    const float* WO = (const float*)d_in[4];
    const float* bO = (const float*)d_in[5];
    const float* WR = (const float*)d_in[6];
    const float* bR = (const float*)d_in[7];
    const int* src  = (const int*)d_in[8];
    const int* dst  = (const int*)d_in[9];
    const int* et   = (const int*)d_in[10];
    const int* nrp  = (n_in > 11) ? (const int*)d_in[11] : nullptr;

    int Dv = in_sizes[3];            // = 64
    int N  = in_sizes[0] / Dv;
    int R  = in_sizes[1] / Dv;
    int E  = in_sizes[8];
    float* out = (float*)d_out;
    float* r_out = out + (size_t)N * Dv;

    int nb   = (N + 255) / 256;      // scan blocks
    int npad = nb * 256;
    int nbZero = 64;
    int nbNT = (N + 63) / 64;

    // 1) fused: zero counters + relation tables + node transform
    k_fused<<<nbZero + R + nbNT, 128>>>(nf, rf, WI, bI, WO, bO, WR, bR,
                                        r_out, N, R, npad, nbZero);
    // 2) degree histogram
    {
        int work = (E >> 2) + 4;
        k_hist<<<(work + 255) / 256, 256>>>(dst, E);
    }
    // 3) two-level exclusive scan
    k_scanA<<<nb, 256>>>();
    k_scanB<<<1, 256>>>(nb);
    // 4) CSR reorder with branch pre-resolution
    k_reorder<<<(E + 255) / 256, 256>>>(src, dst, et, E, N, nrp, R / 2);
    // 5) gather + mean (writes n_out directly)
    {
        long long threads = (long long)N * 32;
        k_gather<<<(int)((threads + 255) / 256), 256>>>(out, N);
    }
}